// round 1
// baseline (speedup 1.0000x reference)
#include <cuda_runtime.h>
#include <cuda_fp16.h>
#include <cstdint>

#define NN 8192
#define FIN 256
#define FOUT 128
#define GAT_ALPHA 0.2f

// ---------------- scratch (allocation-free: __device__ globals) ----------------
__device__ __half g_Whh[NN * FOUT];   // Wh high fp16
__device__ __half g_Whl[NN * FOUT];   // Wh residual fp16
__device__ float  g_s[NN];            // Wh @ a[0:128]
__device__ float  g_t[NN];            // Wh @ a[128:256]

// ---------------- Kernel 1: Wh = h @ W  (fp32), split to fp16 hi/lo, s/t ------
__global__ __launch_bounds__(256) void wh_kernel(const float* __restrict__ h,
                                                 const float* __restrict__ W,
                                                 const float* __restrict__ a)
{
    __shared__ float hs[64 * 36];    // 64 x 32 (+4 pad)
    __shared__ float Ws[32 * 132];   // 32 x 128 (+4 pad)

    const int tid = threadIdx.x;
    const int i0  = blockIdx.x * 64;
    const int tx  = tid & 15;        // col group (8 cols each)
    const int ty  = tid >> 4;        // row group (4 rows each)

    float acc[4][8];
#pragma unroll
    for (int i = 0; i < 4; i++)
#pragma unroll
        for (int u = 0; u < 8; u++) acc[i][u] = 0.f;

    for (int kt = 0; kt < FIN; kt += 32) {
        __syncthreads();
        // load h tile 64x32
#pragma unroll
        for (int q = 0; q < 2; q++) {
            int lin = tid + q * 256;            // float4 index
            int r = lin >> 3, c4 = (lin & 7) * 4;
            *(float4*)&hs[r * 36 + c4] =
                *(const float4*)&h[(size_t)(i0 + r) * FIN + kt + c4];
        }
        // load W tile 32x128
#pragma unroll
        for (int q = 0; q < 4; q++) {
            int lin = tid + q * 256;
            int r = lin >> 5, c4 = (lin & 31) * 4;
            *(float4*)&Ws[r * 132 + c4] =
                *(const float4*)&W[(size_t)(kt + r) * FOUT + c4];
        }
        __syncthreads();
#pragma unroll 4
        for (int k = 0; k < 32; k++) {
            float bv[8];
#pragma unroll
            for (int u = 0; u < 8; u++) bv[u] = Ws[k * 132 + tx * 8 + u];
#pragma unroll
            for (int i = 0; i < 4; i++) {
                float av = hs[(ty * 4 + i) * 36 + k];
#pragma unroll
                for (int u = 0; u < 8; u++) acc[i][u] = fmaf(av, bv[u], acc[i][u]);
            }
        }
    }

    // epilogue: fp16 split + s/t partial dots
    float a1[8], a2[8];
#pragma unroll
    for (int u = 0; u < 8; u++) {
        a1[u] = a[tx * 8 + u];
        a2[u] = a[FOUT + tx * 8 + u];
    }
#pragma unroll
    for (int i = 0; i < 4; i++) {
        int rg = i0 + ty * 4 + i;
        float ps = 0.f, pt = 0.f;
#pragma unroll
        for (int u = 0; u < 8; u++) {
            float v = acc[i][u];
            __half hv = __float2half(v);
            g_Whh[(size_t)rg * FOUT + tx * 8 + u] = hv;
            g_Whl[(size_t)rg * FOUT + tx * 8 + u] = __float2half(v - __half2float(hv));
            ps = fmaf(v, a1[u], ps);
            pt = fmaf(v, a2[u], pt);
        }
        // reduce across 16 threads sharing the row (within half-warp)
#pragma unroll
        for (int off = 1; off < 16; off <<= 1) {
            ps += __shfl_xor_sync(0xffffffffu, ps, off);
            pt += __shfl_xor_sync(0xffffffffu, pt, off);
        }
        if (tx == 0) { g_s[rg] = ps; g_t[rg] = pt; }
    }
}

// ---------------- mma helpers ----------------
__device__ __forceinline__ void ldsm4(uint32_t& r0, uint32_t& r1, uint32_t& r2,
                                      uint32_t& r3, uint32_t addr)
{
    asm volatile("ldmatrix.sync.aligned.m8n8.x4.shared.b16 {%0,%1,%2,%3}, [%4];"
                 : "=r"(r0), "=r"(r1), "=r"(r2), "=r"(r3) : "r"(addr));
}
__device__ __forceinline__ void ldsm4t(uint32_t& r0, uint32_t& r1, uint32_t& r2,
                                       uint32_t& r3, uint32_t addr)
{
    asm volatile("ldmatrix.sync.aligned.m8n8.x4.trans.shared.b16 {%0,%1,%2,%3}, [%4];"
                 : "=r"(r0), "=r"(r1), "=r"(r2), "=r"(r3) : "r"(addr));
}
__device__ __forceinline__ void mma16816(float* c, uint32_t a0, uint32_t a1,
                                         uint32_t a2, uint32_t a3,
                                         uint32_t b0, uint32_t b1)
{
    asm volatile(
        "mma.sync.aligned.m16n8k16.row.col.f32.f16.f16.f32 "
        "{%0,%1,%2,%3}, {%4,%5,%6,%7}, {%8,%9}, {%0,%1,%2,%3};"
        : "+f"(c[0]), "+f"(c[1]), "+f"(c[2]), "+f"(c[3])
        : "r"(a0), "r"(a1), "r"(a2), "r"(a3), "r"(b0), "r"(b1));
}

// ---------------- Kernel 2: fused masked-softmax attention ----------------
// Per CTA: 64 output rows; stream 64 j-tiles of 128; online softmax; two fp16
// MMA passes (Wh hi + lo) into fp32 accumulators; final ELU.
//
// smem layout (dynamic):
//   whh : 128*136 half  (34816 B)
//   whl : 128*136 half  (34816 B)
//   Ps  :  64*136 half  (17408 B)
//   tvals: 128 f32, svals: 64 f32, rscale: 64 f32
#define SM_WHH 0
#define SM_WHL (128 * 136)
#define SM_P   (2 * 128 * 136)
#define SMEM_BYTES ((2 * 128 * 136 + 64 * 136) * 2 + (128 + 64 + 64) * 4)

__global__ __launch_bounds__(256) void attn_kernel(const int* __restrict__ adj,
                                                   float* __restrict__ out)
{
    extern __shared__ __align__(16) char smem[];
    __half* whh  = (__half*)smem;
    __half* whl  = whh + 128 * 136;
    __half* Ps   = whl + 128 * 136;
    float* tvals = (float*)(Ps + 64 * 136);
    float* svals = tvals + 128;
    float* rscale = svals + 64;

    const int tid  = threadIdx.x;
    const int i0   = blockIdx.x * 64;
    const int lane = tid & 31;
    const int wid  = tid >> 5;
    const int wm   = wid >> 1;   // 0..3 : 16-row slab
    const int wn   = wid & 1;    // 0..1 : 64-col slab

    const int er = tid >> 2;     // softmax row 0..63
    const int ej = tid & 3;      // 32-col chunk of the 128-wide tile

    if (tid < 64) svals[tid] = g_s[i0 + tid];

    float m_r = -INFINITY, l_r = 0.f;
    float acc[8][4];
#pragma unroll
    for (int nb = 0; nb < 8; nb++)
#pragma unroll
        for (int v = 0; v < 4; v++) acc[nb][v] = 0.f;

    for (int jt = 0; jt < NN / 128; jt++) {
        const int j0 = jt * 128;
        __syncthreads();   // previous MMA done reading smem; svals ready (1st iter)

        // ---- load Wh hi/lo tiles + t values ----
#pragma unroll
        for (int q = 0; q < 8; q++) {
            int lin = tid + q * 256;
            int r = lin >> 4, c = (lin & 15) * 8;
            *(int4*)&whh[r * 136 + c] = *(const int4*)&g_Whh[(size_t)(j0 + r) * FOUT + c];
            *(int4*)&whl[r * 136 + c] = *(const int4*)&g_Whl[(size_t)(j0 + r) * FOUT + c];
        }
        if (tid < 128) tvals[tid] = g_t[j0 + tid];
        __syncthreads();

        // ---- e / softmax phase ----
        float ev[32];
        const int4* arow =
            (const int4*)(adj + (size_t)(i0 + er) * NN + j0 + ej * 32);
        const float s_r = svals[er];
        float mtile = -INFINITY;
#pragma unroll
        for (int q = 0; q < 8; q++) {
            int4 av = arow[q];
            const int* ai = (const int*)&av;
#pragma unroll
            for (int u = 0; u < 4; u++) {
                int jl = ej * 32 + q * 4 + u;
                float e = s_r + tvals[jl];
                e = fmaxf(e, GAT_ALPHA * e);           // LeakyReLU
                e = (ai[u] > 0) ? e : -INFINITY;       // adjacency mask
                ev[q * 4 + u] = e;
                mtile = fmaxf(mtile, e);
            }
        }
        mtile = fmaxf(mtile, __shfl_xor_sync(0xffffffffu, mtile, 1));
        mtile = fmaxf(mtile, __shfl_xor_sync(0xffffffffu, mtile, 2));
        const float m_new = fmaxf(m_r, mtile);
        const float sc = (m_r == m_new) ? 1.0f : __expf(m_r - m_new);
        float psum = 0.f;
#pragma unroll
        for (int v = 0; v < 32; v++) {
            float p = (ev[v] == -INFINITY) ? 0.f : __expf(ev[v] - m_new);
            psum += p;
            Ps[er * 136 + ej * 32 + v] = __float2half(p);
        }
        psum += __shfl_xor_sync(0xffffffffu, psum, 1);
        psum += __shfl_xor_sync(0xffffffffu, psum, 2);
        l_r = l_r * sc + psum;
        m_r = m_new;
        if (ej == 0) rscale[er] = sc;
        __syncthreads();

        // ---- MMA phase: acc = acc*sc + P @ (Whh + Whl) ----
        const float sc_lo = rscale[wm * 16 + (lane >> 2)];
        const float sc_hi = rscale[wm * 16 + 8 + (lane >> 2)];
#pragma unroll
        for (int nb = 0; nb < 8; nb++) {
            acc[nb][0] *= sc_lo; acc[nb][1] *= sc_lo;
            acc[nb][2] *= sc_hi; acc[nb][3] *= sc_hi;
        }
        const int kA_row = wm * 16 + (lane & 15);
        const int kB_row = (lane & 7) + 8 * ((lane >> 3) & 1);
        const int kB_col = wn * 64 + 8 * (lane >> 4);
#pragma unroll
        for (int ks = 0; ks < 8; ks++) {
            uint32_t a0, a1, a2, a3;
            uint32_t aaddr = (uint32_t)__cvta_generic_to_shared(
                &Ps[kA_row * 136 + ks * 16 + (lane >> 4) * 8]);
            ldsm4(a0, a1, a2, a3, aaddr);
#pragma unroll
            for (int ng = 0; ng < 4; ng++) {
                const int nb0 = ng * 2;
                const int boff = (ks * 16 + kB_row) * 136 + kB_col + ng * 16;
                uint32_t b0, b1, b2, b3;
                uint32_t baddr = (uint32_t)__cvta_generic_to_shared(&whh[boff]);
                ldsm4t(b0, b1, b2, b3, baddr);
                mma16816(acc[nb0],     a0, a1, a2, a3, b0, b1);
                mma16816(acc[nb0 + 1], a0, a1, a2, a3, b2, b3);
                baddr = (uint32_t)__cvta_generic_to_shared(&whl[boff]);
                ldsm4t(b0, b1, b2, b3, baddr);
                mma16816(acc[nb0],     a0, a1, a2, a3, b0, b1);
                mma16816(acc[nb0 + 1], a0, a1, a2, a3, b2, b3);
            }
        }
    }

    __syncthreads();
    if (ej == 0) rscale[er] = 1.0f / l_r;   // reuse as 1/l
    __syncthreads();

    // ---- epilogue: normalize, ELU, store ----
    const float li_lo = rscale[wm * 16 + (lane >> 2)];
    const float li_hi = rscale[wm * 16 + 8 + (lane >> 2)];
    const int rg0 = i0 + wm * 16 + (lane >> 2);
#pragma unroll
    for (int nb = 0; nb < 8; nb++) {
        const int col = wn * 64 + nb * 8 + (lane & 3) * 2;
        float v0 = acc[nb][0] * li_lo, v1 = acc[nb][1] * li_lo;
        float v2 = acc[nb][2] * li_hi, v3 = acc[nb][3] * li_hi;
        v0 = (v0 > 0.f) ? v0 : expm1f(v0);
        v1 = (v1 > 0.f) ? v1 : expm1f(v1);
        v2 = (v2 > 0.f) ? v2 : expm1f(v2);
        v3 = (v3 > 0.f) ? v3 : expm1f(v3);
        out[(size_t)rg0 * FOUT + col]           = v0;
        out[(size_t)rg0 * FOUT + col + 1]       = v1;
        out[(size_t)(rg0 + 8) * FOUT + col]     = v2;
        out[(size_t)(rg0 + 8) * FOUT + col + 1] = v3;
    }
}

// ---------------- launch ----------------
extern "C" void kernel_launch(void* const* d_in, const int* in_sizes, int n_in,
                              void* d_out, int out_size)
{
    const float* h = nullptr;
    const int*   adj = nullptr;
    const float* W = nullptr;
    const float* a = nullptr;
    for (int i = 0; i < n_in; i++) {
        long s = in_sizes[i];
        if (s == (long)NN * FIN)      h   = (const float*)d_in[i];
        else if (s == (long)NN * NN)  adj = (const int*)d_in[i];
        else if (s == (long)FIN * FOUT) W = (const float*)d_in[i];
        else if (s == 2 * FOUT)       a   = (const float*)d_in[i];
    }
    float* out = (float*)d_out;

    cudaFuncSetAttribute(attn_kernel,
                         cudaFuncAttributeMaxDynamicSharedMemorySize, SMEM_BYTES);

    wh_kernel<<<NN / 64, 256>>>(h, W, a);
    attn_kernel<<<NN / 64, 256, SMEM_BYTES>>>(adj, out);
}

// round 3
// speedup vs baseline: 1.4727x; 1.4727x over previous
#include <cuda_runtime.h>
#include <cuda_fp16.h>
#include <cstdint>

#define NN 8192
#define FIN 256
#define FOUT 128
#define GAT_ALPHA 0.2f
#define NW (NN / 32)          // mask words per row = 256

// ---------------- scratch (allocation-free: __device__ globals) ----------------
__device__ __half    g_Whh[NN * FOUT];    // Wh fp16
__device__ float     g_s[NN];             // Wh @ a[0:128]
__device__ float     g_t[NN];             // Wh @ a[128:256]
__device__ unsigned  g_bits[NN * NW];     // adj bit-packed, 8 MB

// ---------------- Kernel 0: bit-pack adjacency -------------------------------
// One warp packs 256 consecutive ints -> 8 mask words via ballot.
// Grid MUST cover NN*NN ints: one block (8 warps) covers 2048 ints.
__global__ __launch_bounds__(256) void pack_kernel(const int* __restrict__ adj)
{
    const int gw   = (blockIdx.x * blockDim.x + threadIdx.x) >> 5;  // global warp
    const int lane = threadIdx.x & 31;
    const size_t base = (size_t)gw * 256;
    unsigned myword = 0;
#pragma unroll
    for (int it = 0; it < 8; it++) {
        int v = adj[base + it * 32 + lane];
        unsigned b = __ballot_sync(0xffffffffu, v > 0);
        if (lane == it) myword = b;
    }
    if (lane < 8) g_bits[(size_t)gw * 8 + lane] = myword;
}

// ---------------- Kernel 1: Wh = h @ W (fp32) -> fp16, s, t ------------------
__global__ __launch_bounds__(256) void wh_kernel(const float* __restrict__ h,
                                                 const float* __restrict__ W,
                                                 const float* __restrict__ a)
{
    __shared__ float hs[64 * 36];
    __shared__ float Ws[32 * 132];

    const int tid = threadIdx.x;
    const int i0  = blockIdx.x * 64;
    const int tx  = tid & 15;
    const int ty  = tid >> 4;

    float acc[4][8];
#pragma unroll
    for (int i = 0; i < 4; i++)
#pragma unroll
        for (int u = 0; u < 8; u++) acc[i][u] = 0.f;

    for (int kt = 0; kt < FIN; kt += 32) {
        __syncthreads();
#pragma unroll
        for (int q = 0; q < 2; q++) {
            int lin = tid + q * 256;
            int r = lin >> 3, c4 = (lin & 7) * 4;
            *(float4*)&hs[r * 36 + c4] =
                *(const float4*)&h[(size_t)(i0 + r) * FIN + kt + c4];
        }
#pragma unroll
        for (int q = 0; q < 4; q++) {
            int lin = tid + q * 256;
            int r = lin >> 5, c4 = (lin & 31) * 4;
            *(float4*)&Ws[r * 132 + c4] =
                *(const float4*)&W[(size_t)(kt + r) * FOUT + c4];
        }
        __syncthreads();
#pragma unroll 4
        for (int k = 0; k < 32; k++) {
            float bv[8];
#pragma unroll
            for (int u = 0; u < 8; u++) bv[u] = Ws[k * 132 + tx * 8 + u];
#pragma unroll
            for (int i = 0; i < 4; i++) {
                float av = hs[(ty * 4 + i) * 36 + k];
#pragma unroll
                for (int u = 0; u < 8; u++) acc[i][u] = fmaf(av, bv[u], acc[i][u]);
            }
        }
    }

    float a1[8], a2[8];
#pragma unroll
    for (int u = 0; u < 8; u++) {
        a1[u] = a[tx * 8 + u];
        a2[u] = a[FOUT + tx * 8 + u];
    }
#pragma unroll
    for (int i = 0; i < 4; i++) {
        int rg = i0 + ty * 4 + i;
        float ps = 0.f, pt = 0.f;
#pragma unroll
        for (int u = 0; u < 8; u++) {
            float v = acc[i][u];
            g_Whh[(size_t)rg * FOUT + tx * 8 + u] = __float2half(v);
            ps = fmaf(v, a1[u], ps);
            pt = fmaf(v, a2[u], pt);
        }
#pragma unroll
        for (int off = 1; off < 16; off <<= 1) {
            ps += __shfl_xor_sync(0xffffffffu, ps, off);
            pt += __shfl_xor_sync(0xffffffffu, pt, off);
        }
        if (tx == 0) { g_s[rg] = ps; g_t[rg] = pt; }
    }
}

// ---------------- mma helpers ----------------
__device__ __forceinline__ void ldsm4(uint32_t& r0, uint32_t& r1, uint32_t& r2,
                                      uint32_t& r3, uint32_t addr)
{
    asm volatile("ldmatrix.sync.aligned.m8n8.x4.shared.b16 {%0,%1,%2,%3}, [%4];"
                 : "=r"(r0), "=r"(r1), "=r"(r2), "=r"(r3) : "r"(addr));
}
__device__ __forceinline__ void ldsm4t(uint32_t& r0, uint32_t& r1, uint32_t& r2,
                                       uint32_t& r3, uint32_t addr)
{
    asm volatile("ldmatrix.sync.aligned.m8n8.x4.trans.shared.b16 {%0,%1,%2,%3}, [%4];"
                 : "=r"(r0), "=r"(r1), "=r"(r2), "=r"(r3) : "r"(addr));
}
__device__ __forceinline__ void mma16816(float* c, uint32_t a0, uint32_t a1,
                                         uint32_t a2, uint32_t a3,
                                         uint32_t b0, uint32_t b1)
{
    asm volatile(
        "mma.sync.aligned.m16n8k16.row.col.f32.f16.f16.f32 "
        "{%0,%1,%2,%3}, {%4,%5,%6,%7}, {%8,%9}, {%0,%1,%2,%3};"
        : "+f"(c[0]), "+f"(c[1]), "+f"(c[2]), "+f"(c[3])
        : "r"(a0), "r"(a1), "r"(a2), "r"(a3), "r"(b0), "r"(b1));
}

// ---------------- Kernel 2: fused masked-softmax attention -------------------
// 32 output rows per CTA (256 CTAs -> 2 resident per SM). Per tile: one mask
// LDG.32 per thread, online softmax, single fp16 MMA pass.
// smem: whh 128x136 half | Ps 32x136 half | tvals 128f | svals 32f | rscale 32f
#define SMEM_BYTES (((128 + 32) * 136) * 2 + (128 + 32 + 32) * 4)

__global__ __launch_bounds__(256) void attn_kernel(float* __restrict__ out)
{
    extern __shared__ __align__(16) char smem[];
    __half* whh   = (__half*)smem;
    __half* Ps    = whh + 128 * 136;
    float*  tvals = (float*)(Ps + 32 * 136);
    float*  svals = tvals + 128;
    float*  rscale = svals + 32;

    const int tid  = threadIdx.x;
    const int i0   = blockIdx.x * 32;
    const int lane = tid & 31;
    const int wid  = tid >> 5;
    const int wm   = wid >> 2;   // 0..1 : 16-row slab
    const int wn   = wid & 3;    // 0..3 : 32-col slab

    const int er = tid >> 3;     // softmax row 0..31
    const int ej = tid & 7;      // 16-col chunk of the 128-wide tile

    if (tid < 32) svals[tid] = g_s[i0 + tid];

    float m_r = -INFINITY, l_r = 0.f;
    float acc[4][4];
#pragma unroll
    for (int nb = 0; nb < 4; nb++)
#pragma unroll
        for (int v = 0; v < 4; v++) acc[nb][v] = 0.f;

    const unsigned* brow = g_bits + (size_t)(i0 + er) * NW;

    for (int jt = 0; jt < NN / 128; jt++) {
        const int j0 = jt * 128;
        __syncthreads();                    // prev MMA done with whh/Ps

        // ---- load Wh tile + t values ----
#pragma unroll
        for (int q = 0; q < 8; q++) {
            int lin = tid + q * 256;
            int r = lin >> 4, c = (lin & 15) * 8;
            *(int4*)&whh[r * 136 + c] =
                *(const int4*)&g_Whh[(size_t)(j0 + r) * FOUT + c];
        }
        if (tid < 128) tvals[tid] = g_t[j0 + tid];
        __syncthreads();

        // ---- e / online-softmax phase (one mask LDG per thread) ----
        unsigned w = brow[jt * 4 + (ej >> 1)];
        unsigned mhalf = (ej & 1) ? (w >> 16) : (w & 0xffffu);
        const float s_r = svals[er];
        float ev[16];
        float mtile = -INFINITY;
#pragma unroll
        for (int u = 0; u < 16; u++) {
            float e = s_r + tvals[ej * 16 + u];
            e = fmaxf(e, GAT_ALPHA * e);                 // LeakyReLU
            e = ((mhalf >> u) & 1u) ? e : -INFINITY;     // adjacency mask
            ev[u] = e;
            mtile = fmaxf(mtile, e);
        }
        mtile = fmaxf(mtile, __shfl_xor_sync(0xffffffffu, mtile, 1));
        mtile = fmaxf(mtile, __shfl_xor_sync(0xffffffffu, mtile, 2));
        mtile = fmaxf(mtile, __shfl_xor_sync(0xffffffffu, mtile, 4));
        const float m_new = fmaxf(m_r, mtile);
        const float sc = (m_r == m_new) ? 1.0f : __expf(m_r - m_new);
        float psum = 0.f;
#pragma unroll
        for (int v = 0; v < 8; v++) {
            float p0 = (ev[2 * v]     == -INFINITY) ? 0.f : __expf(ev[2 * v]     - m_new);
            float p1 = (ev[2 * v + 1] == -INFINITY) ? 0.f : __expf(ev[2 * v + 1] - m_new);
            psum += p0 + p1;
            *(__half2*)&Ps[er * 136 + ej * 16 + 2 * v] = __floats2half2_rn(p0, p1);
        }
        psum += __shfl_xor_sync(0xffffffffu, psum, 1);
        psum += __shfl_xor_sync(0xffffffffu, psum, 2);
        psum += __shfl_xor_sync(0xffffffffu, psum, 4);
        l_r = l_r * sc + psum;
        m_r = m_new;
        if (ej == 0) rscale[er] = sc;
        __syncthreads();

        // ---- MMA phase: acc = acc*sc + P @ Wh ----
        const float sc_lo = rscale[wm * 16 + (lane >> 2)];
        const float sc_hi = rscale[wm * 16 + 8 + (lane >> 2)];
#pragma unroll
        for (int nb = 0; nb < 4; nb++) {
            acc[nb][0] *= sc_lo; acc[nb][1] *= sc_lo;
            acc[nb][2] *= sc_hi; acc[nb][3] *= sc_hi;
        }
        const int kA_row = wm * 16 + (lane & 15);
        const int kB_row = (lane & 7) + 8 * ((lane >> 3) & 1);
        const int kB_col = wn * 32 + 8 * (lane >> 4);
#pragma unroll
        for (int ks = 0; ks < 8; ks++) {
            uint32_t a0, a1, a2, a3;
            uint32_t aaddr = (uint32_t)__cvta_generic_to_shared(
                &Ps[kA_row * 136 + ks * 16 + (lane >> 4) * 8]);
            ldsm4(a0, a1, a2, a3, aaddr);
#pragma unroll
            for (int ng = 0; ng < 2; ng++) {
                const int nb0 = ng * 2;
                const int boff = (ks * 16 + kB_row) * 136 + kB_col + ng * 16;
                uint32_t b0, b1, b2, b3;
                uint32_t baddr = (uint32_t)__cvta_generic_to_shared(&whh[boff]);
                ldsm4t(b0, b1, b2, b3, baddr);
                mma16816(acc[nb0],     a0, a1, a2, a3, b0, b1);
                mma16816(acc[nb0 + 1], a0, a1, a2, a3, b2, b3);
            }
        }
    }

    __syncthreads();
    if (ej == 0) rscale[er] = 1.0f / l_r;
    __syncthreads();

    // ---- epilogue: normalize, ELU, store ----
    const float li_lo = rscale[wm * 16 + (lane >> 2)];
    const float li_hi = rscale[wm * 16 + 8 + (lane >> 2)];
    const int rg0 = i0 + wm * 16 + (lane >> 2);
#pragma unroll
    for (int nb = 0; nb < 4; nb++) {
        const int col = wn * 32 + nb * 8 + (lane & 3) * 2;
        float v0 = acc[nb][0] * li_lo, v1 = acc[nb][1] * li_lo;
        float v2 = acc[nb][2] * li_hi, v3 = acc[nb][3] * li_hi;
        v0 = (v0 > 0.f) ? v0 : expm1f(v0);
        v1 = (v1 > 0.f) ? v1 : expm1f(v1);
        v2 = (v2 > 0.f) ? v2 : expm1f(v2);
        v3 = (v3 > 0.f) ? v3 : expm1f(v3);
        out[(size_t)rg0 * FOUT + col]           = v0;
        out[(size_t)rg0 * FOUT + col + 1]       = v1;
        out[(size_t)(rg0 + 8) * FOUT + col]     = v2;
        out[(size_t)(rg0 + 8) * FOUT + col + 1] = v3;
    }
}

// ---------------- launch ----------------
extern "C" void kernel_launch(void* const* d_in, const int* in_sizes, int n_in,
                              void* d_out, int out_size)
{
    const float* h = nullptr;
    const int*   adj = nullptr;
    const float* W = nullptr;
    const float* a = nullptr;
    for (int i = 0; i < n_in; i++) {
        long s = in_sizes[i];
        if (s == (long)NN * FIN)        h   = (const float*)d_in[i];
        else if (s == (long)NN * NN)    adj = (const int*)d_in[i];
        else if (s == (long)FIN * FOUT) W   = (const float*)d_in[i];
        else if (s == 2 * FOUT)         a   = (const float*)d_in[i];
    }
    float* out = (float*)d_out;

    cudaFuncSetAttribute(attn_kernel,
                         cudaFuncAttributeMaxDynamicSharedMemorySize, SMEM_BYTES);

    // NN*NN ints total; one block (8 warps x 256 ints) covers 2048 ints.
    pack_kernel<<<NN * NN / 2048, 256>>>(adj);
    wh_kernel<<<NN / 64, 256>>>(h, W, a);
    attn_kernel<<<NN / 32, 256, SMEM_BYTES>>>(out);
}

// round 4
// speedup vs baseline: 1.6432x; 1.1158x over previous
#include <cuda_runtime.h>
#include <cuda_fp16.h>
#include <cstdint>

#define NN 8192
#define FIN 256
#define FOUT 128
#define GAT_ALPHA 0.2f
#define NW (NN / 32)            // mask words per row = 256
#define NT (NN / 128)           // j-tiles = 64
#define LOG2E 1.4426950408889634f

// ---------------- scratch (allocation-free: __device__ globals) ----------------
__device__ __half    g_Whh[NN * FOUT];    // Wh fp16
__device__ float     g_s[NN];             // Wh @ a[0:128]   (raw)
__device__ float     g_t[NN];             // (Wh @ a[128:256]) * log2(e)
__device__ unsigned  g_bits[NN * NW];     // adj bit-packed, 8 MB
__device__ unsigned  g_tmax_u = 0;        // order-encoded float max of raw t

__device__ __forceinline__ unsigned fenc(float f) {
    int i = __float_as_int(f);
    return (i >= 0) ? ((unsigned)i + 0x80000000u) : (unsigned)(~i);
}
__device__ __forceinline__ float fdec(unsigned u) {
    return (u >= 0x80000000u) ? __int_as_float((int)(u - 0x80000000u))
                              : __int_as_float((int)~u);
}

// ---------------- Kernel A: fused Wh-GEMM (blocks 0..127) + adj pack ---------
__global__ __launch_bounds__(256) void prep_kernel(const float* __restrict__ h,
                                                   const float* __restrict__ W,
                                                   const float* __restrict__ a,
                                                   const int* __restrict__ adj)
{
    __shared__ float hs[64 * 36];
    __shared__ float Ws[32 * 132];
    const int tid = threadIdx.x;

    if (blockIdx.x >= 128) {
        // ---- pack branch: one warp packs 256 ints -> 8 mask words ----
        const int pb   = blockIdx.x - 128;
        const int gw   = pb * 8 + (tid >> 5);
        const int lane = tid & 31;
        const size_t base = (size_t)gw * 256;
        unsigned myword = 0;
#pragma unroll
        for (int it = 0; it < 8; it++) {
            int v = adj[base + it * 32 + lane];
            unsigned b = __ballot_sync(0xffffffffu, v > 0);
            if (lane == it) myword = b;
        }
        if (lane < 8) g_bits[(size_t)gw * 8 + lane] = myword;
        return;
    }

    // ---- Wh branch ----
    const int i0 = blockIdx.x * 64;
    const int tx = tid & 15;
    const int ty = tid >> 4;

    float acc[4][8];
#pragma unroll
    for (int i = 0; i < 4; i++)
#pragma unroll
        for (int u = 0; u < 8; u++) acc[i][u] = 0.f;

    for (int kt = 0; kt < FIN; kt += 32) {
        __syncthreads();
#pragma unroll
        for (int q = 0; q < 2; q++) {
            int lin = tid + q * 256;
            int r = lin >> 3, c4 = (lin & 7) * 4;
            *(float4*)&hs[r * 36 + c4] =
                *(const float4*)&h[(size_t)(i0 + r) * FIN + kt + c4];
        }
#pragma unroll
        for (int q = 0; q < 4; q++) {
            int lin = tid + q * 256;
            int r = lin >> 5, c4 = (lin & 31) * 4;
            *(float4*)&Ws[r * 132 + c4] =
                *(const float4*)&W[(size_t)(kt + r) * FOUT + c4];
        }
        __syncthreads();
#pragma unroll 4
        for (int k = 0; k < 32; k++) {
            float bv[8];
#pragma unroll
            for (int u = 0; u < 8; u++) bv[u] = Ws[k * 132 + tx * 8 + u];
#pragma unroll
            for (int i = 0; i < 4; i++) {
                float av = hs[(ty * 4 + i) * 36 + k];
#pragma unroll
                for (int u = 0; u < 8; u++) acc[i][u] = fmaf(av, bv[u], acc[i][u]);
            }
        }
    }

    float a1[8], a2[8];
#pragma unroll
    for (int u = 0; u < 8; u++) {
        a1[u] = a[tx * 8 + u];
        a2[u] = a[FOUT + tx * 8 + u];
    }
#pragma unroll
    for (int i = 0; i < 4; i++) {
        int rg = i0 + ty * 4 + i;
        float ps = 0.f, pt = 0.f;
#pragma unroll
        for (int u = 0; u < 8; u++) {
            float v = acc[i][u];
            g_Whh[(size_t)rg * FOUT + tx * 8 + u] = __float2half(v);
            ps = fmaf(v, a1[u], ps);
            pt = fmaf(v, a2[u], pt);
        }
#pragma unroll
        for (int off = 1; off < 16; off <<= 1) {
            ps += __shfl_xor_sync(0xffffffffu, ps, off);
            pt += __shfl_xor_sync(0xffffffffu, pt, off);
        }
        if (tx == 0) {
            g_s[rg] = ps;
            g_t[rg] = pt * LOG2E;
            atomicMax(&g_tmax_u, fenc(pt));   // raw-t max (idempotent across replays)
        }
    }
}

// ---------------- mma helpers ----------------
__device__ __forceinline__ void ldsm4(uint32_t& r0, uint32_t& r1, uint32_t& r2,
                                      uint32_t& r3, uint32_t addr)
{
    asm volatile("ldmatrix.sync.aligned.m8n8.x4.shared.b16 {%0,%1,%2,%3}, [%4];"
                 : "=r"(r0), "=r"(r1), "=r"(r2), "=r"(r3) : "r"(addr));
}
__device__ __forceinline__ void ldsm4t(uint32_t& r0, uint32_t& r1, uint32_t& r2,
                                       uint32_t& r3, uint32_t addr)
{
    asm volatile("ldmatrix.sync.aligned.m8n8.x4.trans.shared.b16 {%0,%1,%2,%3}, [%4];"
                 : "=r"(r0), "=r"(r1), "=r"(r2), "=r"(r3) : "r"(addr));
}
__device__ __forceinline__ void mma16816(float* c, uint32_t a0, uint32_t a1,
                                         uint32_t a2, uint32_t a3,
                                         uint32_t b0, uint32_t b1)
{
    asm volatile(
        "mma.sync.aligned.m16n8k16.row.col.f32.f16.f16.f32 "
        "{%0,%1,%2,%3}, {%4,%5,%6,%7}, {%8,%9}, {%0,%1,%2,%3};"
        : "+f"(c[0]), "+f"(c[1]), "+f"(c[2]), "+f"(c[3])
        : "r"(a0), "r"(a1), "r"(a2), "r"(a3), "r"(b0), "r"(b1));
}
__device__ __forceinline__ float ex2(float x) {
    float r;
    asm("ex2.approx.f32 %0, %1;" : "=f"(r) : "f"(x));
    return r;
}
__device__ __forceinline__ void cpa16(uint32_t dst, const void* src) {
    asm volatile("cp.async.cg.shared.global [%0], [%1], 16;" :: "r"(dst), "l"(src));
}

// ---------------- Kernel B: fixed-max fused attention ------------------------
// 32 rows/CTA, 256 CTAs. Double-buffered Wh/t tiles via cp.async; double-
// buffered P; fixed per-row softmax max (no rescaling ever); 2 barriers/tile.
// smem: whh 2x128x136 h | Ps 2x32x136 h | tv 2x128 f | linv 32 f
#define SMEM_BYTES ((2 * 128 * 136 + 2 * 32 * 136) * 2 + (2 * 128 + 32) * 4)

__global__ __launch_bounds__(256, 2) void attn_kernel(float* __restrict__ out)
{
    extern __shared__ __align__(16) char smem[];
    __half* whh  = (__half*)smem;                  // [2][128*136]
    __half* Ps   = whh + 2 * 128 * 136;            // [2][32*136]
    float*  tv   = (float*)(Ps + 2 * 32 * 136);    // [2][128]
    float*  linv = tv + 2 * 128;

    const int tid  = threadIdx.x;
    const int i0   = blockIdx.x * 32;
    const int lane = tid & 31;
    const int wid  = tid >> 5;
    const int wm   = wid >> 2;
    const int wn   = wid & 3;
    const int er   = tid >> 3;     // softmax row 0..31
    const int ej   = tid & 7;      // 16-col chunk

    // per-thread loop-invariant softmax constants
    const float s_r  = g_s[i0 + er];
    const float tmax = fdec(g_tmax_u);
    const float x    = s_r + tmax;
    const float mhat = fmaxf(x, GAT_ALPHA * x);          // >= max_j lrelu(s+t)
    const float A    = (s_r - mhat) * LOG2E;
    const float B    = (GAT_ALPHA * s_r - mhat) * LOG2E; // + 0.2*t'  (t' pre-scaled)

    const unsigned* brow = g_bits + (size_t)(i0 + er) * NW;

    float l_acc = 0.f;
    float acc[4][4];
#pragma unroll
    for (int nb = 0; nb < 4; nb++)
#pragma unroll
        for (int v = 0; v < 4; v++) acc[nb][v] = 0.f;

    // ---- prefetch tile 0 into buffer 0 ----
    {
#pragma unroll
        for (int q = 0; q < 8; q++) {
            int lin = tid + q * 256;
            int r = lin >> 4, c = (lin & 15) * 8;
            cpa16((uint32_t)__cvta_generic_to_shared(&whh[r * 136 + c]),
                  &g_Whh[(size_t)r * FOUT + c]);
        }
        if (tid < 32)
            cpa16((uint32_t)__cvta_generic_to_shared(&tv[tid * 4]), &g_t[tid * 4]);
        asm volatile("cp.async.commit_group;");
    }

    const int kA_row = wm * 16 + (lane & 15);
    const int kB_row = (lane & 7) + 8 * ((lane >> 3) & 1);
    const int kB_col = wn * 32 + 8 * (lane >> 4);

    for (int jt = 0; jt < NT; jt++) {
        const int b = jt & 1;
        __half* whb = whh + b * 128 * 136;
        __half* Psb = Ps + b * 32 * 136;
        float*  tvb = tv + b * 128;

        asm volatile("cp.async.wait_group 0;");
        __syncthreads();                       // (1) tile jt resident; prev MMA done

        // prefetch tile jt+1 into other buffer (overlaps this tile's compute)
        if (jt + 1 < NT) {
            const int j1 = (jt + 1) * 128;
            __half* whn = whh + (b ^ 1) * 128 * 136;
            float*  tvn = tv + (b ^ 1) * 128;
#pragma unroll
            for (int q = 0; q < 8; q++) {
                int lin = tid + q * 256;
                int r = lin >> 4, c = (lin & 15) * 8;
                cpa16((uint32_t)__cvta_generic_to_shared(&whn[r * 136 + c]),
                      &g_Whh[(size_t)(j1 + r) * FOUT + c]);
            }
            if (tid < 32)
                cpa16((uint32_t)__cvta_generic_to_shared(&tvn[tid * 4]),
                      &g_t[j1 + tid * 4]);
        }
        asm volatile("cp.async.commit_group;");

        // ---- e-phase: p = exp2(max(A + t', fma(0.2, t', B))), masked ----
        unsigned w = brow[jt * 4 + (ej >> 1)];
        unsigned mhalf = (ej & 1) ? (w >> 16) : (w & 0xffffu);
        float4 tq[4];
#pragma unroll
        for (int q = 0; q < 4; q++) tq[q] = *(float4*)&tvb[ej * 16 + q * 4];
        uint32_t pk[8];
#pragma unroll
        for (int q = 0; q < 4; q++) {
            const float* tqa = (const float*)&tq[q];
#pragma unroll
            for (int d = 0; d < 2; d++) {
                float t0 = tqa[d * 2], t1 = tqa[d * 2 + 1];
                float e0 = fmaxf(A + t0, fmaf(GAT_ALPHA, t0, B));
                float e1 = fmaxf(A + t1, fmaf(GAT_ALPHA, t1, B));
                int u = q * 4 + d * 2;
                e0 = ((mhalf >> u) & 1u) ? e0 : -INFINITY;
                e1 = ((mhalf >> (u + 1)) & 1u) ? e1 : -INFINITY;
                float p0 = ex2(e0), p1 = ex2(e1);
                l_acc += p0 + p1;
                pk[q * 2 + d] = __float_as_uint(0.f);
                ((__half2*)pk)[q * 2 + d] = __floats2half2_rn(p0, p1);
            }
        }
        *(uint4*)&Psb[er * 136 + ej * 16]     = *(uint4*)&pk[0];
        *(uint4*)&Psb[er * 136 + ej * 16 + 8] = *(uint4*)&pk[4];
        __syncthreads();                       // (2) Ps[b] ready

        // ---- MMA: acc += P @ Wh ----
#pragma unroll
        for (int ks = 0; ks < 8; ks++) {
            uint32_t a0, a1, a2, a3;
            uint32_t aaddr = (uint32_t)__cvta_generic_to_shared(
                &Psb[kA_row * 136 + ks * 16 + (lane >> 4) * 8]);
            ldsm4(a0, a1, a2, a3, aaddr);
#pragma unroll
            for (int ng = 0; ng < 2; ng++) {
                const int nb0 = ng * 2;
                const int boff = (ks * 16 + kB_row) * 136 + kB_col + ng * 16;
                uint32_t b0, b1, b2, b3;
                uint32_t baddr = (uint32_t)__cvta_generic_to_shared(&whb[boff]);
                ldsm4t(b0, b1, b2, b3, baddr);
                mma16816(acc[nb0],     a0, a1, a2, a3, b0, b1);
                mma16816(acc[nb0 + 1], a0, a1, a2, a3, b2, b3);
            }
        }
    }

    // ---- final l reduction (8 threads per row, same warp) ----
    l_acc += __shfl_xor_sync(0xffffffffu, l_acc, 1);
    l_acc += __shfl_xor_sync(0xffffffffu, l_acc, 2);
    l_acc += __shfl_xor_sync(0xffffffffu, l_acc, 4);
    __syncthreads();
    if (ej == 0) linv[er] = 1.0f / l_acc;
    __syncthreads();

    // ---- epilogue: normalize, ELU, store ----
    const float li_lo = linv[wm * 16 + (lane >> 2)];
    const float li_hi = linv[wm * 16 + 8 + (lane >> 2)];
    const int rg0 = i0 + wm * 16 + (lane >> 2);
#pragma unroll
    for (int nb = 0; nb < 4; nb++) {
        const int col = wn * 32 + nb * 8 + (lane & 3) * 2;
        float v0 = acc[nb][0] * li_lo, v1 = acc[nb][1] * li_lo;
        float v2 = acc[nb][2] * li_hi, v3 = acc[nb][3] * li_hi;
        v0 = (v0 > 0.f) ? v0 : expm1f(v0);
        v1 = (v1 > 0.f) ? v1 : expm1f(v1);
        v2 = (v2 > 0.f) ? v2 : expm1f(v2);
        v3 = (v3 > 0.f) ? v3 : expm1f(v3);
        out[(size_t)rg0 * FOUT + col]           = v0;
        out[(size_t)rg0 * FOUT + col + 1]       = v1;
        out[(size_t)(rg0 + 8) * FOUT + col]     = v2;
        out[(size_t)(rg0 + 8) * FOUT + col + 1] = v3;
    }
}

// ---------------- launch ----------------
extern "C" void kernel_launch(void* const* d_in, const int* in_sizes, int n_in,
                              void* d_out, int out_size)
{
    const float* h = nullptr;
    const int*   adj = nullptr;
    const float* W = nullptr;
    const float* a = nullptr;
    for (int i = 0; i < n_in; i++) {
        long s = in_sizes[i];
        if (s == (long)NN * FIN)        h   = (const float*)d_in[i];
        else if (s == (long)NN * NN)    adj = (const int*)d_in[i];
        else if (s == (long)FIN * FOUT) W   = (const float*)d_in[i];
        else if (s == 2 * FOUT)         a   = (const float*)d_in[i];
    }
    float* out = (float*)d_out;

    cudaFuncSetAttribute(attn_kernel,
                         cudaFuncAttributeMaxDynamicSharedMemorySize, SMEM_BYTES);

    // 128 Wh blocks first, then 32768 pack blocks (overlap compute with stream)
    prep_kernel<<<128 + NN * NN / 2048, 256>>>(h, W, a, adj);
    attn_kernel<<<NN / 32, 256, SMEM_BYTES>>>(out);
}

// round 5
// speedup vs baseline: 1.7383x; 1.0578x over previous
#include <cuda_runtime.h>
#include <cuda_fp16.h>
#include <cstdint>

#define NN 8192
#define FIN 256
#define FOUT 128
#define GAT_ALPHA 0.2f
#define NT (NN / 128)           // j-tiles = 64
#define LOG2E 1.4426950408889634f

// ---------------- scratch (allocation-free: __device__ globals) ----------------
__device__ __half    g_Whh[NN * FOUT];    // Wh fp16
__device__ float     g_s[NN];             // Wh @ a[0:128]   (raw)
__device__ float     g_t[NN];             // (Wh @ a[128:256]) * log2(e)
__device__ unsigned  g_tmax_u = 0;        // order-encoded float max of raw t

__device__ __forceinline__ unsigned fenc(float f) {
    int i = __float_as_int(f);
    return (i >= 0) ? ((unsigned)i + 0x80000000u) : (unsigned)(~i);
}
__device__ __forceinline__ float fdec(unsigned u) {
    return (u >= 0x80000000u) ? __int_as_float((int)(u - 0x80000000u))
                              : __int_as_float((int)~u);
}

// ---------------- Kernel 1: Wh = h @ W (fp32) -> fp16, s, t ------------------
__global__ __launch_bounds__(256) void wh_kernel(const float* __restrict__ h,
                                                 const float* __restrict__ W,
                                                 const float* __restrict__ a)
{
    __shared__ float hs[64 * 36];
    __shared__ float Ws[32 * 132];

    const int tid = threadIdx.x;
    const int i0  = blockIdx.x * 64;
    const int tx  = tid & 15;
    const int ty  = tid >> 4;

    float acc[4][8];
#pragma unroll
    for (int i = 0; i < 4; i++)
#pragma unroll
        for (int u = 0; u < 8; u++) acc[i][u] = 0.f;

    for (int kt = 0; kt < FIN; kt += 32) {
        __syncthreads();
#pragma unroll
        for (int q = 0; q < 2; q++) {
            int lin = tid + q * 256;
            int r = lin >> 3, c4 = (lin & 7) * 4;
            *(float4*)&hs[r * 36 + c4] =
                *(const float4*)&h[(size_t)(i0 + r) * FIN + kt + c4];
        }
#pragma unroll
        for (int q = 0; q < 4; q++) {
            int lin = tid + q * 256;
            int r = lin >> 5, c4 = (lin & 31) * 4;
            *(float4*)&Ws[r * 132 + c4] =
                *(const float4*)&W[(size_t)(kt + r) * FOUT + c4];
        }
        __syncthreads();
#pragma unroll 4
        for (int k = 0; k < 32; k++) {
            float bv[8];
#pragma unroll
            for (int u = 0; u < 8; u++) bv[u] = Ws[k * 132 + tx * 8 + u];
#pragma unroll
            for (int i = 0; i < 4; i++) {
                float av = hs[(ty * 4 + i) * 36 + k];
#pragma unroll
                for (int u = 0; u < 8; u++) acc[i][u] = fmaf(av, bv[u], acc[i][u]);
            }
        }
    }

    float a1[8], a2[8];
#pragma unroll
    for (int u = 0; u < 8; u++) {
        a1[u] = a[tx * 8 + u];
        a2[u] = a[FOUT + tx * 8 + u];
    }
#pragma unroll
    for (int i = 0; i < 4; i++) {
        int rg = i0 + ty * 4 + i;
        float ps = 0.f, pt = 0.f;
#pragma unroll
        for (int u = 0; u < 8; u++) {
            float v = acc[i][u];
            g_Whh[(size_t)rg * FOUT + tx * 8 + u] = __float2half(v);
            ps = fmaf(v, a1[u], ps);
            pt = fmaf(v, a2[u], pt);
        }
#pragma unroll
        for (int off = 1; off < 16; off <<= 1) {
            ps += __shfl_xor_sync(0xffffffffu, ps, off);
            pt += __shfl_xor_sync(0xffffffffu, pt, off);
        }
        if (tx == 0) {
            g_s[rg] = ps;
            g_t[rg] = pt * LOG2E;
            atomicMax(&g_tmax_u, fenc(pt));   // idempotent across replays
        }
    }
}

// ---------------- mma helpers ----------------
__device__ __forceinline__ void ldsm4(uint32_t& r0, uint32_t& r1, uint32_t& r2,
                                      uint32_t& r3, uint32_t addr)
{
    asm volatile("ldmatrix.sync.aligned.m8n8.x4.shared.b16 {%0,%1,%2,%3}, [%4];"
                 : "=r"(r0), "=r"(r1), "=r"(r2), "=r"(r3) : "r"(addr));
}
__device__ __forceinline__ void ldsm4t(uint32_t& r0, uint32_t& r1, uint32_t& r2,
                                       uint32_t& r3, uint32_t addr)
{
    asm volatile("ldmatrix.sync.aligned.m8n8.x4.trans.shared.b16 {%0,%1,%2,%3}, [%4];"
                 : "=r"(r0), "=r"(r1), "=r"(r2), "=r"(r3) : "r"(addr));
}
__device__ __forceinline__ void mma16816(float* c, uint32_t a0, uint32_t a1,
                                         uint32_t a2, uint32_t a3,
                                         uint32_t b0, uint32_t b1)
{
    asm volatile(
        "mma.sync.aligned.m16n8k16.row.col.f32.f16.f16.f32 "
        "{%0,%1,%2,%3}, {%4,%5,%6,%7}, {%8,%9}, {%0,%1,%2,%3};"
        : "+f"(c[0]), "+f"(c[1]), "+f"(c[2]), "+f"(c[3])
        : "r"(a0), "r"(a1), "r"(a2), "r"(a3), "r"(b0), "r"(b1));
}
__device__ __forceinline__ float ex2(float x) {
    float r;
    asm("ex2.approx.f32 %0, %1;" : "=f"(r) : "f"(x));
    return r;
}
__device__ __forceinline__ void cpa16(uint32_t dst, const void* src) {
    asm volatile("cp.async.cg.shared.global [%0], [%1], 16;" :: "r"(dst), "l"(src));
}

// ---------------- Kernel 2: fixed-max fused attention ------------------------
// 32 rows/CTA, 256 CTAs (all resident: 2/SM). adj read directly from GMEM with
// one-tile-ahead register prefetch (4x LDG.128/thread). Double-buffered
// Wh/t/P smem tiles; fixed per-row softmax max; 1 full + 1 half barrier/tile.
#define SMEM_BYTES ((2 * 128 * 136 + 2 * 32 * 136) * 2 + (2 * 128 + 32) * 4)

__global__ __launch_bounds__(256, 2) void attn_kernel(const int* __restrict__ adj,
                                                      float* __restrict__ out)
{
    extern __shared__ __align__(16) char smem[];
    __half* whh  = (__half*)smem;                  // [2][128*136]
    __half* Ps   = whh + 2 * 128 * 136;            // [2][32*136]
    float*  tv   = (float*)(Ps + 2 * 32 * 136);    // [2][128]
    float*  linv = tv + 2 * 128;

    const int tid  = threadIdx.x;
    const int i0   = blockIdx.x * 32;
    const int lane = tid & 31;
    const int wid  = tid >> 5;
    const int wm   = wid >> 2;
    const int wn   = wid & 3;
    const int er   = tid >> 3;     // softmax row 0..31
    const int ej   = tid & 7;      // 16-col chunk

    // loop-invariant softmax constants
    const float s_r  = g_s[i0 + er];
    const float tmax = fdec(g_tmax_u);
    const float x    = s_r + tmax;
    const float mhat = fmaxf(x, GAT_ALPHA * x);
    const float A    = (s_r - mhat) * LOG2E;
    const float B    = (GAT_ALPHA * s_r - mhat) * LOG2E;

    const int4* arow = (const int4*)(adj + (size_t)(i0 + er) * NN + ej * 16);
    // per tile stride in int4 units: 128 ints = 32 int4

    float l_acc = 0.f;
    float acc[4][4];
#pragma unroll
    for (int nb = 0; nb < 4; nb++)
#pragma unroll
        for (int v = 0; v < 4; v++) acc[nb][v] = 0.f;

    // ---- prefetch tile 0: Wh/t via cp.async, adj via LDG ----
#pragma unroll
    for (int q = 0; q < 8; q++) {
        int lin = tid + q * 256;
        int r = lin >> 4, c = (lin & 15) * 8;
        cpa16((uint32_t)__cvta_generic_to_shared(&whh[r * 136 + c]),
              &g_Whh[(size_t)r * FOUT + c]);
    }
    if (tid < 32)
        cpa16((uint32_t)__cvta_generic_to_shared(&tv[tid * 4]), &g_t[tid * 4]);
    asm volatile("cp.async.commit_group;");

    int4 cur[4], nxt[4];
#pragma unroll
    for (int q = 0; q < 4; q++) cur[q] = arow[q];

    const int kA_row = wm * 16 + (lane & 15);
    const int kB_row = (lane & 7) + 8 * ((lane >> 3) & 1);
    const int kB_col = wn * 32 + 8 * (lane >> 4);

    for (int jt = 0; jt < NT; jt++) {
        const int b = jt & 1;
        __half* whb = whh + b * 128 * 136;
        __half* Psb = Ps + b * 32 * 136;
        float*  tvb = tv + b * 128;

        asm volatile("cp.async.wait_group 0;");
        __syncthreads();            // tile jt resident; MMA(jt-1) done everywhere

        // prefetch tile jt+1 (Wh/t cp.async + adj LDG) — overlaps this tile
        if (jt + 1 < NT) {
            const int j1 = (jt + 1) * 128;
            __half* whn = whh + (b ^ 1) * 128 * 136;
            float*  tvn = tv + (b ^ 1) * 128;
#pragma unroll
            for (int q = 0; q < 8; q++) {
                int lin = tid + q * 256;
                int r = lin >> 4, c = (lin & 15) * 8;
                cpa16((uint32_t)__cvta_generic_to_shared(&whn[r * 136 + c]),
                      &g_Whh[(size_t)(j1 + r) * FOUT + c]);
            }
            if (tid < 32)
                cpa16((uint32_t)__cvta_generic_to_shared(&tvn[tid * 4]),
                      &g_t[j1 + tid * 4]);
#pragma unroll
            for (int q = 0; q < 4; q++) nxt[q] = arow[(size_t)(jt + 1) * 32 + q];
        }
        asm volatile("cp.async.commit_group;");

        // ---- e-phase: p = exp2(max(A + t', fma(0.2, t', B))), adj-masked ----
#pragma unroll
        for (int q = 0; q < 4; q++) {
            const int* ai = (const int*)&cur[q];
            float4 tq = *(float4*)&tvb[ej * 16 + q * 4];
            const float* tqa = (const float*)&tq;
#pragma unroll
            for (int d = 0; d < 2; d++) {
                float t0 = tqa[d * 2], t1 = tqa[d * 2 + 1];
                float e0 = fmaxf(A + t0, fmaf(GAT_ALPHA, t0, B));
                float e1 = fmaxf(A + t1, fmaf(GAT_ALPHA, t1, B));
                e0 = (ai[d * 2]     > 0) ? e0 : -INFINITY;
                e1 = (ai[d * 2 + 1] > 0) ? e1 : -INFINITY;
                float p0 = ex2(e0), p1 = ex2(e1);
                l_acc += p0 + p1;
                *(__half2*)&Psb[er * 136 + ej * 16 + q * 4 + d * 2] =
                    __floats2half2_rn(p0, p1);
            }
        }
#pragma unroll
        for (int q = 0; q < 4; q++) cur[q] = nxt[q];

        // half-CTA barrier: rows 0-15 <-> threads/warps 0-127; rows 16-31 <-> 128-255
        if (wm == 0) asm volatile("bar.sync 1, 128;" ::: "memory");
        else         asm volatile("bar.sync 2, 128;" ::: "memory");

        // ---- MMA: acc += P @ Wh ----
#pragma unroll
        for (int ks = 0; ks < 8; ks++) {
            uint32_t a0, a1, a2, a3;
            uint32_t aaddr = (uint32_t)__cvta_generic_to_shared(
                &Psb[kA_row * 136 + ks * 16 + (lane >> 4) * 8]);
            ldsm4(a0, a1, a2, a3, aaddr);
#pragma unroll
            for (int ng = 0; ng < 2; ng++) {
                const int nb0 = ng * 2;
                const int boff = (ks * 16 + kB_row) * 136 + kB_col + ng * 16;
                uint32_t b0, b1, b2, b3;
                uint32_t baddr = (uint32_t)__cvta_generic_to_shared(&whb[boff]);
                ldsm4t(b0, b1, b2, b3, baddr);
                mma16816(acc[nb0],     a0, a1, a2, a3, b0, b1);
                mma16816(acc[nb0 + 1], a0, a1, a2, a3, b2, b3);
            }
        }
    }

    // ---- final l reduction (8 threads/row, same warp) ----
    l_acc += __shfl_xor_sync(0xffffffffu, l_acc, 1);
    l_acc += __shfl_xor_sync(0xffffffffu, l_acc, 2);
    l_acc += __shfl_xor_sync(0xffffffffu, l_acc, 4);
    __syncthreads();
    if (ej == 0) linv[er] = 1.0f / l_acc;
    __syncthreads();

    // ---- epilogue: normalize, ELU, store ----
    const float li_lo = linv[wm * 16 + (lane >> 2)];
    const float li_hi = linv[wm * 16 + 8 + (lane >> 2)];
    const int rg0 = i0 + wm * 16 + (lane >> 2);
#pragma unroll
    for (int nb = 0; nb < 4; nb++) {
        const int col = wn * 32 + nb * 8 + (lane & 3) * 2;
        float v0 = acc[nb][0] * li_lo, v1 = acc[nb][1] * li_lo;
        float v2 = acc[nb][2] * li_hi, v3 = acc[nb][3] * li_hi;
        v0 = (v0 > 0.f) ? v0 : expm1f(v0);
        v1 = (v1 > 0.f) ? v1 : expm1f(v1);
        v2 = (v2 > 0.f) ? v2 : expm1f(v2);
        v3 = (v3 > 0.f) ? v3 : expm1f(v3);
        out[(size_t)rg0 * FOUT + col]           = v0;
        out[(size_t)rg0 * FOUT + col + 1]       = v1;
        out[(size_t)(rg0 + 8) * FOUT + col]     = v2;
        out[(size_t)(rg0 + 8) * FOUT + col + 1] = v3;
    }
}

// ---------------- launch ----------------
extern "C" void kernel_launch(void* const* d_in, const int* in_sizes, int n_in,
                              void* d_out, int out_size)
{
    const float* h = nullptr;
    const int*   adj = nullptr;
    const float* W = nullptr;
    const float* a = nullptr;
    for (int i = 0; i < n_in; i++) {
        long s = in_sizes[i];
        if (s == (long)NN * FIN)        h   = (const float*)d_in[i];
        else if (s == (long)NN * NN)    adj = (const int*)d_in[i];
        else if (s == (long)FIN * FOUT) W   = (const float*)d_in[i];
        else if (s == 2 * FOUT)         a   = (const float*)d_in[i];
    }
    float* out = (float*)d_out;

    cudaFuncSetAttribute(attn_kernel,
                         cudaFuncAttributeMaxDynamicSharedMemorySize, SMEM_BYTES);

    wh_kernel<<<NN / 64, 256>>>(h, W, a);
    attn_kernel<<<NN / 32, 256, SMEM_BYTES>>>(adj, out);
}

// round 8
// speedup vs baseline: 1.7413x; 1.0017x over previous
#include <cuda_runtime.h>
#include <cuda_fp16.h>
#include <cstdint>

#define NN 8192
#define FIN 256
#define FOUT 128
#define GAT_ALPHA 0.2f
#define NT (NN / 128)           // j-tiles = 64
#define LOG2E 1.4426950408889634f

// ---------------- scratch (allocation-free: __device__ globals) ----------------
__device__ __half    g_Whh[NN * FOUT];    // Wh fp16
__device__ float     g_s[NN];             // Wh @ a[0:128]   (raw)
__device__ float     g_t[NN];             // (Wh @ a[128:256]) * log2(e)
__device__ unsigned  g_tmax_u = 0;        // order-encoded float max of raw t

__device__ __forceinline__ unsigned fenc(float f) {
    int i = __float_as_int(f);
    return (i >= 0) ? ((unsigned)i + 0x80000000u) : (unsigned)(~i);
}
__device__ __forceinline__ float fdec(unsigned u) {
    return (u >= 0x80000000u) ? __int_as_float((int)(u - 0x80000000u))
                              : __int_as_float((int)~u);
}

// ---------------- Kernel 1: Wh = h @ W (fp32) -> fp16, s, t ------------------
__global__ __launch_bounds__(256) void wh_kernel(const float* __restrict__ h,
                                                 const float* __restrict__ W,
                                                 const float* __restrict__ a)
{
    __shared__ float hs[64 * 36];
    __shared__ float Ws[32 * 132];

    const int tid = threadIdx.x;
    const int i0  = blockIdx.x * 64;
    const int tx  = tid & 15;
    const int ty  = tid >> 4;

    float acc[4][8];
#pragma unroll
    for (int i = 0; i < 4; i++)
#pragma unroll
        for (int u = 0; u < 8; u++) acc[i][u] = 0.f;

    for (int kt = 0; kt < FIN; kt += 32) {
        __syncthreads();
#pragma unroll
        for (int q = 0; q < 2; q++) {
            int lin = tid + q * 256;
            int r = lin >> 3, c4 = (lin & 7) * 4;
            *(float4*)&hs[r * 36 + c4] =
                *(const float4*)&h[(size_t)(i0 + r) * FIN + kt + c4];
        }
#pragma unroll
        for (int q = 0; q < 4; q++) {
            int lin = tid + q * 256;
            int r = lin >> 5, c4 = (lin & 31) * 4;
            *(float4*)&Ws[r * 132 + c4] =
                *(const float4*)&W[(size_t)(kt + r) * FOUT + c4];
        }
        __syncthreads();
#pragma unroll 4
        for (int k = 0; k < 32; k++) {
            float bv[8];
#pragma unroll
            for (int u = 0; u < 8; u++) bv[u] = Ws[k * 132 + tx * 8 + u];
#pragma unroll
            for (int i = 0; i < 4; i++) {
                float av = hs[(ty * 4 + i) * 36 + k];
#pragma unroll
                for (int u = 0; u < 8; u++) acc[i][u] = fmaf(av, bv[u], acc[i][u]);
            }
        }
    }

    float a1[8], a2[8];
#pragma unroll
    for (int u = 0; u < 8; u++) {
        a1[u] = a[tx * 8 + u];
        a2[u] = a[FOUT + tx * 8 + u];
    }
#pragma unroll
    for (int i = 0; i < 4; i++) {
        int rg = i0 + ty * 4 + i;
        float ps = 0.f, pt = 0.f;
#pragma unroll
        for (int u = 0; u < 8; u++) {
            float v = acc[i][u];
            g_Whh[(size_t)rg * FOUT + tx * 8 + u] = __float2half(v);
            ps = fmaf(v, a1[u], ps);
            pt = fmaf(v, a2[u], pt);
        }
#pragma unroll
        for (int off = 1; off < 16; off <<= 1) {
            ps += __shfl_xor_sync(0xffffffffu, ps, off);
            pt += __shfl_xor_sync(0xffffffffu, pt, off);
        }
        if (tx == 0) {
            g_s[rg] = ps;
            g_t[rg] = pt * LOG2E;
            atomicMax(&g_tmax_u, fenc(pt));   // idempotent across replays
        }
    }
}

// ---------------- mma helpers ----------------
__device__ __forceinline__ void ldsm4(uint32_t& r0, uint32_t& r1, uint32_t& r2,
                                      uint32_t& r3, uint32_t addr)
{
    asm volatile("ldmatrix.sync.aligned.m8n8.x4.shared.b16 {%0,%1,%2,%3}, [%4];"
                 : "=r"(r0), "=r"(r1), "=r"(r2), "=r"(r3) : "r"(addr));
}
__device__ __forceinline__ void ldsm4t(uint32_t& r0, uint32_t& r1, uint32_t& r2,
                                       uint32_t& r3, uint32_t addr)
{
    asm volatile("ldmatrix.sync.aligned.m8n8.x4.trans.shared.b16 {%0,%1,%2,%3}, [%4];"
                 : "=r"(r0), "=r"(r1), "=r"(r2), "=r"(r3) : "r"(addr));
}
__device__ __forceinline__ void mma16816(float* c, uint32_t a0, uint32_t a1,
                                         uint32_t a2, uint32_t a3,
                                         uint32_t b0, uint32_t b1)
{
    asm volatile(
        "mma.sync.aligned.m16n8k16.row.col.f32.f16.f16.f32 "
        "{%0,%1,%2,%3}, {%4,%5,%6,%7}, {%8,%9}, {%0,%1,%2,%3};"
        : "+f"(c[0]), "+f"(c[1]), "+f"(c[2]), "+f"(c[3])
        : "r"(a0), "r"(a1), "r"(a2), "r"(a3), "r"(b0), "r"(b1));
}
__device__ __forceinline__ float ex2(float x) {
    float r;
    asm("ex2.approx.f32 %0, %1;" : "=f"(r) : "f"(x));
    return r;
}
__device__ __forceinline__ void cpa16(uint32_t dst, const void* src) {
    asm volatile("cp.async.cg.shared.global [%0], [%1], 16;" :: "r"(dst), "l"(src));
}

// ---------------- Kernel 2: fixed-max fused attention ------------------------
// 32 rows/CTA, 256 CTAs (all resident: 2/SM). adj read directly from GMEM with
// one-tile-ahead register prefetch (4x LDG.128/thread). Double-buffered
// Wh/t/P smem tiles; fixed per-row softmax max; 1 full + 1 half barrier/tile.
#define SMEM_BYTES ((2 * 128 * 136 + 2 * 32 * 136) * 2 + (2 * 128 + 32) * 4)

__global__ __launch_bounds__(256, 2) void attn_kernel(const int* __restrict__ adj,
                                                      float* __restrict__ out)
{
    extern __shared__ __align__(16) char smem[];
    __half* whh  = (__half*)smem;                  // [2][128*136]
    __half* Ps   = whh + 2 * 128 * 136;            // [2][32*136]
    float*  tv   = (float*)(Ps + 2 * 32 * 136);    // [2][128]
    float*  linv = tv + 2 * 128;

    const int tid  = threadIdx.x;
    const int i0   = blockIdx.x * 32;
    const int lane = tid & 31;
    const int wid  = tid >> 5;
    const int wm   = wid >> 2;
    const int wn   = wid & 3;
    const int er   = tid >> 3;     // softmax row 0..31
    const int ej   = tid & 7;      // 16-col chunk

    // loop-invariant softmax constants
    const float s_r  = g_s[i0 + er];
    const float tmax = fdec(g_tmax_u);
    const float x    = s_r + tmax;
    const float mhat = fmaxf(x, GAT_ALPHA * x);
    const float A    = (s_r - mhat) * LOG2E;
    const float B    = (GAT_ALPHA * s_r - mhat) * LOG2E;

    const int4* arow = (const int4*)(adj + (size_t)(i0 + er) * NN + ej * 16);
    // per tile stride in int4 units: 128 ints = 32 int4

    float l_acc = 0.f;
    float acc[4][4];
#pragma unroll
    for (int nb = 0; nb < 4; nb++)
#pragma unroll
        for (int v = 0; v < 4; v++) acc[nb][v] = 0.f;

    // ---- prefetch tile 0: Wh/t via cp.async, adj via LDG ----
#pragma unroll
    for (int q = 0; q < 8; q++) {
        int lin = tid + q * 256;
        int r = lin >> 4, c = (lin & 15) * 8;
        cpa16((uint32_t)__cvta_generic_to_shared(&whh[r * 136 + c]),
              &g_Whh[(size_t)r * FOUT + c]);
    }
    if (tid < 32)
        cpa16((uint32_t)__cvta_generic_to_shared(&tv[tid * 4]), &g_t[tid * 4]);
    asm volatile("cp.async.commit_group;");

    int4 cur[4], nxt[4];
#pragma unroll
    for (int q = 0; q < 4; q++) cur[q] = arow[q];

    const int kA_row = wm * 16 + (lane & 15);
    const int kB_row = (lane & 7) + 8 * ((lane >> 3) & 1);
    const int kB_col = wn * 32 + 8 * (lane >> 4);

    for (int jt = 0; jt < NT; jt++) {
        const int b = jt & 1;
        __half* whb = whh + b * 128 * 136;
        __half* Psb = Ps + b * 32 * 136;
        float*  tvb = tv + b * 128;

        asm volatile("cp.async.wait_group 0;");
        __syncthreads();            // tile jt resident; MMA(jt-1) done everywhere

        // prefetch tile jt+1 (Wh/t cp.async + adj LDG) — overlaps this tile
        if (jt + 1 < NT) {
            const int j1 = (jt + 1) * 128;
            __half* whn = whh + (b ^ 1) * 128 * 136;
            float*  tvn = tv + (b ^ 1) * 128;
#pragma unroll
            for (int q = 0; q < 8; q++) {
                int lin = tid + q * 256;
                int r = lin >> 4, c = (lin & 15) * 8;
                cpa16((uint32_t)__cvta_generic_to_shared(&whn[r * 136 + c]),
                      &g_Whh[(size_t)(j1 + r) * FOUT + c]);
            }
            if (tid < 32)
                cpa16((uint32_t)__cvta_generic_to_shared(&tvn[tid * 4]),
                      &g_t[j1 + tid * 4]);
#pragma unroll
            for (int q = 0; q < 4; q++) nxt[q] = arow[(size_t)(jt + 1) * 32 + q];
        }
        asm volatile("cp.async.commit_group;");

        // ---- e-phase: p = exp2(max(A + t', fma(0.2, t', B))), adj-masked ----
#pragma unroll
        for (int q = 0; q < 4; q++) {
            const int* ai = (const int*)&cur[q];
            float4 tq = *(float4*)&tvb[ej * 16 + q * 4];
            const float* tqa = (const float*)&tq;
#pragma unroll
            for (int d = 0; d < 2; d++) {
                float t0 = tqa[d * 2], t1 = tqa[d * 2 + 1];
                float e0 = fmaxf(A + t0, fmaf(GAT_ALPHA, t0, B));
                float e1 = fmaxf(A + t1, fmaf(GAT_ALPHA, t1, B));
                e0 = (ai[d * 2]     > 0) ? e0 : -INFINITY;
                e1 = (ai[d * 2 + 1] > 0) ? e1 : -INFINITY;
                float p0 = ex2(e0), p1 = ex2(e1);
                l_acc += p0 + p1;
                *(__half2*)&Psb[er * 136 + ej * 16 + q * 4 + d * 2] =
                    __floats2half2_rn(p0, p1);
            }
        }
#pragma unroll
        for (int q = 0; q < 4; q++) cur[q] = nxt[q];

        // half-CTA barrier: rows 0-15 <-> threads/warps 0-127; rows 16-31 <-> 128-255
        if (wm == 0) asm volatile("bar.sync 1, 128;" ::: "memory");
        else         asm volatile("bar.sync 2, 128;" ::: "memory");

        // ---- MMA: acc += P @ Wh ----
#pragma unroll
        for (int ks = 0; ks < 8; ks++) {
            uint32_t a0, a1, a2, a3;
            uint32_t aaddr = (uint32_t)__cvta_generic_to_shared(
                &Psb[kA_row * 136 + ks * 16 + (lane >> 4) * 8]);
            ldsm4(a0, a1, a2, a3, aaddr);
#pragma unroll
            for (int ng = 0; ng < 2; ng++) {
                const int nb0 = ng * 2;
                const int boff = (ks * 16 + kB_row) * 136 + kB_col + ng * 16;
                uint32_t b0, b1, b2, b3;
                uint32_t baddr = (uint32_t)__cvta_generic_to_shared(&whb[boff]);
                ldsm4t(b0, b1, b2, b3, baddr);
                mma16816(acc[nb0],     a0, a1, a2, a3, b0, b1);
                mma16816(acc[nb0 + 1], a0, a1, a2, a3, b2, b3);
            }
        }
    }

    // ---- final l reduction (8 threads/row, same warp) ----
    l_acc += __shfl_xor_sync(0xffffffffu, l_acc, 1);
    l_acc += __shfl_xor_sync(0xffffffffu, l_acc, 2);
    l_acc += __shfl_xor_sync(0xffffffffu, l_acc, 4);
    __syncthreads();
    if (ej == 0) linv[er] = 1.0f / l_acc;
    __syncthreads();

    // ---- epilogue: normalize, ELU, store ----
    const float li_lo = linv[wm * 16 + (lane >> 2)];
    const float li_hi = linv[wm * 16 + 8 + (lane >> 2)];
    const int rg0 = i0 + wm * 16 + (lane >> 2);
#pragma unroll
    for (int nb = 0; nb < 4; nb++) {
        const int col = wn * 32 + nb * 8 + (lane & 3) * 2;
        float v0 = acc[nb][0] * li_lo, v1 = acc[nb][1] * li_lo;
        float v2 = acc[nb][2] * li_hi, v3 = acc[nb][3] * li_hi;
        v0 = (v0 > 0.f) ? v0 : expm1f(v0);
        v1 = (v1 > 0.f) ? v1 : expm1f(v1);
        v2 = (v2 > 0.f) ? v2 : expm1f(v2);
        v3 = (v3 > 0.f) ? v3 : expm1f(v3);
        out[(size_t)rg0 * FOUT + col]           = v0;
        out[(size_t)rg0 * FOUT + col + 1]       = v1;
        out[(size_t)(rg0 + 8) * FOUT + col]     = v2;
        out[(size_t)(rg0 + 8) * FOUT + col + 1] = v3;
    }
}

// ---------------- launch ----------------
extern "C" void kernel_launch(void* const* d_in, const int* in_sizes, int n_in,
                              void* d_out, int out_size)
{
    const float* h = nullptr;
    const int*   adj = nullptr;
    const float* W = nullptr;
    const float* a = nullptr;
    for (int i = 0; i < n_in; i++) {
        long s = in_sizes[i];
        if (s == (long)NN * FIN)        h   = (const float*)d_in[i];
        else if (s == (long)NN * NN)    adj = (const int*)d_in[i];
        else if (s == (long)FIN * FOUT) W   = (const float*)d_in[i];
        else if (s == 2 * FOUT)         a   = (const float*)d_in[i];
    }
    float* out = (float*)d_out;

    cudaFuncSetAttribute(attn_kernel,
                         cudaFuncAttributeMaxDynamicSharedMemorySize, SMEM_BYTES);

    wh_kernel<<<NN / 64, 256>>>(h, W, a);
    attn_kernel<<<NN / 32, 256, SMEM_BYTES>>>(adj, out);
}